// round 6
// baseline (speedup 1.0000x reference)
#include <cuda_runtime.h>
#include <cstdint>

#define NB   2
#define NPTS 8192
#define CIN  128
#define COUT 128
#define KNN  21
#define FULLM 0xffffffffu
#define SENT 0xFFFFFFFFFFFFFFFFull
#define FINF __int_as_float(0x7f800000)

// ---------------- scratch (device globals; no allocation allowed) -------------
__device__ __align__(16) float g_Ageo [NB * NPTS * 128];
__device__ __align__(16) float g_Btgeo[NB * NPTS * 128];
__device__ __align__(16) float g_Afeat[NB * NPTS * 128];
__device__ __align__(16) float g_Btfeat[NB * NPTS * 128];
__device__ int   g_idx[NB * NPTS * KNN];
__device__ __align__(16) float g_scale[256];
__device__ __align__(16) float g_shift[256];

// ---------------- BN constants ----------------
__global__ void constants_kernel(const float* __restrict__ gg, const float* __restrict__ bg,
                                 const float* __restrict__ mg, const float* __restrict__ vg,
                                 const float* __restrict__ gf, const float* __restrict__ bf,
                                 const float* __restrict__ mf, const float* __restrict__ vf) {
    int c = threadIdx.x;
    if (c < 128) {
        float inv = gg[c] * rsqrtf(vg[c] + 1e-5f);
        g_scale[c] = inv;
        g_shift[c] = bg[c] - mg[c] * inv;
    } else {
        int o = c - 128;
        float inv = gf[o] * rsqrtf(vf[o] + 1e-5f);
        g_scale[c] = inv;
        g_shift[c] = bf[o] - mf[o] * inv;
    }
}

// ---------------- geo precompute --------------------------------------------
__global__ void geo_precompute_kernel(const float* __restrict__ xyz,
                                      const float* __restrict__ W_geo) {
    int g = blockIdx.x * blockDim.x + threadIdx.x;
    int o = g & 127;
    int r = g >> 7;
    int n = r & (NPTS - 1);
    int b = r >> 13;
    const float* p = xyz + ((size_t)b * NPTS + n) * 3;
    float x = p[0], y = p[1], z = p[2];
    float w0 = W_geo[o * 6 + 0], w1 = W_geo[o * 6 + 1], w2 = W_geo[o * 6 + 2];
    float w3 = W_geo[o * 6 + 3], w4 = W_geo[o * 6 + 4], w5 = W_geo[o * 6 + 5];
    size_t base = ((size_t)b * NPTS + n) * 128 + o;
    g_Ageo [base] = fmaf(w0 - w3, x, fmaf(w1 - w4, y, (w2 - w5) * z));
    g_Btgeo[base] = fmaf(w3, x, fmaf(w4, y, w5 * z));
}

// ---------------- feat precompute GEMMs (float4 smem reads) ------------------
__global__ void __launch_bounds__(128) feat_gemm_kernel(const float* __restrict__ f,
                                                        const float* __restrict__ W_feat) {
    __shared__ __align__(16) float sf[128][32];
    int b  = blockIdx.y;
    int n0 = blockIdx.x * 32;

    for (int t = threadIdx.x; t < 128 * 32; t += 128) {
        int c = t >> 5, n = t & 31;
        sf[c][n] = f[((size_t)b * 128 + c) * NPTS + n0 + n];
    }
    __syncthreads();

    int o = threadIdx.x;
    float accA[32], accB[32];
#pragma unroll
    for (int n = 0; n < 32; ++n) { accA[n] = 0.f; accB[n] = 0.f; }

    for (int c = 0; c < 128; ++c) {
        float w1 = __ldg(&W_feat[o * 256 + c]);
        float w2 = __ldg(&W_feat[o * 256 + 128 + c]);
        float wm = w1 - w2;
        const float4* row = (const float4*)sf[c];
#pragma unroll
        for (int n4 = 0; n4 < 8; ++n4) {
            float4 v = row[n4];
            accA[n4 * 4 + 0] = fmaf(wm, v.x, accA[n4 * 4 + 0]);
            accB[n4 * 4 + 0] = fmaf(w2, v.x, accB[n4 * 4 + 0]);
            accA[n4 * 4 + 1] = fmaf(wm, v.y, accA[n4 * 4 + 1]);
            accB[n4 * 4 + 1] = fmaf(w2, v.y, accB[n4 * 4 + 1]);
            accA[n4 * 4 + 2] = fmaf(wm, v.z, accA[n4 * 4 + 2]);
            accB[n4 * 4 + 2] = fmaf(w2, v.z, accB[n4 * 4 + 2]);
            accA[n4 * 4 + 3] = fmaf(wm, v.w, accA[n4 * 4 + 3]);
            accB[n4 * 4 + 3] = fmaf(w2, v.w, accB[n4 * 4 + 3]);
        }
    }
#pragma unroll
    for (int n = 0; n < 32; ++n) {
        size_t base = ((size_t)b * NPTS + n0 + n) * 128 + o;
        g_Afeat [base] = accA[n];
        g_Btfeat[base] = accB[n];
    }
}

// ---------------- KNN: two-pass, 4 queries/warp, per-lane top-2 bound --------
#define KNN_CHUNK 1024
#define QCAP 96
#define QPW 4

__global__ void __launch_bounds__(256) knn_kernel(const float* __restrict__ xyz) {
    __shared__ float4 sc[KNN_CHUNK];
    __shared__ unsigned long long sQ[8 * QPW][QCAP];

    int b    = blockIdx.y;
    int warp = threadIdx.x >> 5;
    int lane = threadIdx.x & 31;
    int qb   = blockIdx.x * (8 * QPW) + warp * QPW;

    const float* base = xyz + (size_t)b * NPTS * 3;
    float qx[QPW], qy[QPW], qz[QPW], qd[QPW];
#pragma unroll
    for (int t = 0; t < QPW; ++t) {
        qx[t] = base[(qb + t) * 3 + 0];
        qy[t] = base[(qb + t) * 3 + 1];
        qz[t] = base[(qb + t) * 3 + 2];
        qd[t] = fmaf(qx[t], qx[t], fmaf(qy[t], qy[t], qz[t] * qz[t]));
    }

    float b0[QPW], b1[QPW];     // lane's two smallest distances per query
#pragma unroll
    for (int t = 0; t < QPW; ++t) { b0[t] = FINF; b1[t] = FINF; }

    // -------- pass 1: per-lane top-2, branch-free --------
    for (int cb = 0; cb < NPTS; cb += KNN_CHUNK) {
        __syncthreads();
        for (int i = threadIdx.x; i < KNN_CHUNK; i += 256) {
            int j = cb + i;
            float x = base[j * 3 + 0];
            float y = base[j * 3 + 1];
            float z = base[j * 3 + 2];
            float d2 = fmaf(x, x, fmaf(y, y, z * z));
            sc[i] = make_float4(x, y, z, d2);
        }
        __syncthreads();

#pragma unroll 4
        for (int i = lane; i < KNN_CHUNK; i += 32) {
            float4 c = sc[i];
#pragma unroll
            for (int t = 0; t < QPW; ++t) {
                float dot  = fmaf(qx[t], c.x, fmaf(qy[t], c.y, qz[t] * c.z));
                float dist = fmaf(-2.f, dot, qd[t] + c.w);   // reference formula
                b1[t] = fminf(b1[t], fmaxf(b0[t], dist));
                b0[t] = fminf(b0[t], dist);
            }
        }
    }

    // tau[t] = 21st smallest of the 64-value union (subset => tau >= true d21)
    float tau[QPW];
#pragma unroll 1
    for (int t = 0; t < QPW; ++t) {
        float u0 = b0[t], u1 = b1[t], mv;
#pragma unroll 1
        for (int r = 0; r < KNN; ++r) {
            mv = u0;
#pragma unroll
            for (int off = 16; off; off >>= 1)
                mv = fminf(mv, __shfl_xor_sync(FULLM, mv, off));
            unsigned msk = __ballot_sync(FULLM, u0 == mv);
            if (lane == __ffs(msk) - 1) { u0 = u1; u1 = FINF; }
        }
        tau[t] = mv;
    }

    // -------- pass 2: collect all dist <= tau, in index order --------
    unsigned cnt[QPW];
    unsigned long long* Q[QPW];
#pragma unroll
    for (int t = 0; t < QPW; ++t) { cnt[t] = 0; Q[t] = sQ[warp * QPW + t]; }

    for (int cb = 0; cb < NPTS; cb += KNN_CHUNK) {
        __syncthreads();
        for (int i = threadIdx.x; i < KNN_CHUNK; i += 256) {
            int j = cb + i;
            float x = base[j * 3 + 0];
            float y = base[j * 3 + 1];
            float z = base[j * 3 + 2];
            float d2 = fmaf(x, x, fmaf(y, y, z * z));
            sc[i] = make_float4(x, y, z, d2);
        }
        __syncthreads();

#pragma unroll 2
        for (int i = lane; i < KNN_CHUNK; i += 32) {
            float4 c = sc[i];
#pragma unroll
            for (int t = 0; t < QPW; ++t) {
                float dot  = fmaf(qx[t], c.x, fmaf(qy[t], c.y, qz[t] * c.z));
                float dist = fmaf(-2.f, dot, qd[t] + c.w);
                bool hit = (dist <= tau[t]);
                unsigned m = __ballot_sync(FULLM, hit);
                if (m) {
                    if (hit) {
                        unsigned u = __float_as_uint(dist);
                        u ^= ((unsigned)((int)u >> 31)) | 0x80000000u;  // order flip
                        unsigned off = cnt[t] + __popc(m & ((1u << lane) - 1u));
                        if (off < QCAP)
                            Q[t][off] = ((unsigned long long)u << 32)
                                        | (unsigned)(cb + i);
                    }
                    cnt[t] += __popc(m);
                }
            }
        }
    }
    __syncwarp();

    // -------- final: exact top-21 of each queue by (dist, idx) key --------
#pragma unroll 1
    for (int t = 0; t < QPW; ++t) {
        int n = (int)cnt[t];
        if (n > QCAP) n = QCAP;
        unsigned long long k0 = (lane      < n) ? Q[t][lane]      : SENT;
        unsigned long long k1 = (lane + 32 < n) ? Q[t][lane + 32] : SENT;
        unsigned long long k2 = (lane + 64 < n) ? Q[t][lane + 64] : SENT;
        int myidx = 0;
#pragma unroll 1
        for (int r = 0; r < KNN; ++r) {
            unsigned long long lo = (k0 < k1) ? k0 : k1;
            unsigned long long best = (lo < k2) ? lo : k2;
            int bsrc = lane;
#pragma unroll
            for (int off = 16; off; off >>= 1) {
                unsigned long long ov = __shfl_xor_sync(FULLM, best, off);
                int os = __shfl_xor_sync(FULLM, bsrc, off);
                if (ov < best || (ov == best && os < bsrc)) { best = ov; bsrc = os; }
            }
            if (lane == r) myidx = (int)(best & 0xffffffffu);
            if (lane == bsrc) {           // keys unique (distinct idx)
                if      (k0 == best) k0 = SENT;
                else if (k1 == best) k1 = SENT;
                else                 k2 = SENT;
            }
        }
        if (lane < KNN)
            g_idx[((size_t)b * NPTS + qb + t) * KNN + lane] = myidx;
    }
}

// ---------------- gather-max + epilogue --------------------------------------
__device__ __forceinline__ float4 fmax4(float4 a, float4 b) {
    return make_float4(fmaxf(a.x, b.x), fmaxf(a.y, b.y),
                       fmaxf(a.z, b.z), fmaxf(a.w, b.w));
}

__global__ void __launch_bounds__(256) gather_max_kernel(float* __restrict__ out) {
    __shared__ int   sidx[32][KNN];
    __shared__ float sout[256 * 33];

    int b    = blockIdx.y;
    int n0   = blockIdx.x * 32;
    int warp = threadIdx.x >> 5;
    int lane = threadIdx.x & 31;

    for (int t = threadIdx.x; t < 32 * KNN; t += 256)
        sidx[t / KNN][t % KNN] = g_idx[((size_t)b * NPTS + n0) * KNN + t];
    __syncthreads();

    const float4* BG = (const float4*)g_Btgeo;
    const float4* BF = (const float4*)g_Btfeat;
    const float4* AG = (const float4*)g_Ageo;
    const float4* AF = (const float4*)g_Afeat;
    const float4* S4 = (const float4*)g_scale;
    const float4* H4 = (const float4*)g_shift;

    float4 scg = S4[lane],        shg = H4[lane];
    float4 scf = S4[32 + lane],   shf = H4[32 + lane];

    for (int pi = 0; pi < 4; ++pi) {
        int p = warp * 4 + pi;
        int n = n0 + p;
        float4 mg = make_float4(-3.4e38f, -3.4e38f, -3.4e38f, -3.4e38f);
        float4 mf = mg;
#pragma unroll
        for (int k = 0; k < KNN; ++k) {
            int j = sidx[p][k];
            size_t col = ((size_t)b * NPTS + j) * 32 + lane;
            mg = fmax4(mg, BG[col]);
            mf = fmax4(mf, BF[col]);
        }
        size_t acol = ((size_t)b * NPTS + n) * 32 + lane;
        float4 ag = AG[acol];
        float4 af = AF[acol];

        int cg = lane * 4;
        sout[(cg + 0) * 33 + p] = fmaxf(fmaf(mg.x + ag.x, scg.x, shg.x), 0.f);
        sout[(cg + 1) * 33 + p] = fmaxf(fmaf(mg.y + ag.y, scg.y, shg.y), 0.f);
        sout[(cg + 2) * 33 + p] = fmaxf(fmaf(mg.z + ag.z, scg.z, shg.z), 0.f);
        sout[(cg + 3) * 33 + p] = fmaxf(fmaf(mg.w + ag.w, scg.w, shg.w), 0.f);
        int cf = 128 + lane * 4;
        sout[(cf + 0) * 33 + p] = fmaxf(fmaf(mf.x + af.x, scf.x, shf.x), 0.f);
        sout[(cf + 1) * 33 + p] = fmaxf(fmaf(mf.y + af.y, scf.y, shf.y), 0.f);
        sout[(cf + 2) * 33 + p] = fmaxf(fmaf(mf.z + af.z, scf.z, shf.z), 0.f);
        sout[(cf + 3) * 33 + p] = fmaxf(fmaf(mf.w + af.w, scf.w, shf.w), 0.f);
    }
    __syncthreads();

    for (int c = warp; c < 256; c += 8)
        out[((size_t)b * 256 + c) * NPTS + n0 + lane] = sout[c * 33 + lane];
}

// ---------------- launch ------------------------------------------------------
extern "C" void kernel_launch(void* const* d_in, const int* in_sizes, int n_in,
                              void* d_out, int out_size) {
    const float* xyz    = (const float*)d_in[0];
    const float* f      = (const float*)d_in[1];
    const float* W_geo  = (const float*)d_in[2];
    const float* g_geo  = (const float*)d_in[3];
    const float* b_geo  = (const float*)d_in[4];
    const float* m_geo  = (const float*)d_in[5];
    const float* v_geo  = (const float*)d_in[6];
    const float* W_feat = (const float*)d_in[7];
    const float* g_feat = (const float*)d_in[8];
    const float* b_feat = (const float*)d_in[9];
    const float* m_feat = (const float*)d_in[10];
    const float* v_feat = (const float*)d_in[11];
    float* out = (float*)d_out;

    constants_kernel<<<1, 256>>>(g_geo, b_geo, m_geo, v_geo,
                                 g_feat, b_feat, m_feat, v_feat);
    geo_precompute_kernel<<<(NB * NPTS * 128) / 256, 256>>>(xyz, W_geo);
    feat_gemm_kernel<<<dim3(NPTS / 32, NB), 128>>>(f, W_feat);
    knn_kernel<<<dim3(NPTS / 32, NB), 256>>>(xyz);
    gather_max_kernel<<<dim3(NPTS / 32, NB), 256>>>(out);
}

// round 7
// speedup vs baseline: 1.1894x; 1.1894x over previous
#include <cuda_runtime.h>
#include <cstdint>

#define NB   2
#define NPTS 8192
#define CIN  128
#define COUT 128
#define KNN  21
#define FULLM 0xffffffffu
#define SENT 0xFFFFFFFFFFFFFFFFull
#define FINF __int_as_float(0x7f800000)

// ---------------- scratch (device globals; no allocation allowed) -------------
__device__ __align__(16) float g_Ageo [NB * NPTS * 128];
__device__ __align__(16) float g_Btgeo[NB * NPTS * 128];
__device__ __align__(16) float g_Afeat[NB * NPTS * 128];
__device__ __align__(16) float g_Btfeat[NB * NPTS * 128];
__device__ int   g_idx[NB * NPTS * KNN];
__device__ __align__(16) float g_scale[256];
__device__ __align__(16) float g_shift[256];

// ------------- fused precompute: constants + geo + feat GEMM ------------------
__global__ void __launch_bounds__(128) precompute_kernel(
        const float* __restrict__ xyz, const float* __restrict__ f,
        const float* __restrict__ W_geo, const float* __restrict__ W_feat,
        const float* __restrict__ gg, const float* __restrict__ bg,
        const float* __restrict__ mg, const float* __restrict__ vg,
        const float* __restrict__ gf, const float* __restrict__ bf,
        const float* __restrict__ mf, const float* __restrict__ vf) {
    __shared__ __align__(16) float sf[128][32];
    __shared__ float sxyz[32][3];
    int b  = blockIdx.y;
    int n0 = blockIdx.x * 32;
    int o  = threadIdx.x;

    // BN constants (one block only)
    if (blockIdx.x == 0 && blockIdx.y == 0) {
        {
            float inv = gg[o] * rsqrtf(vg[o] + 1e-5f);
            g_scale[o] = inv;
            g_shift[o] = bg[o] - mg[o] * inv;
        }
        {
            float inv = gf[o] * rsqrtf(vf[o] + 1e-5f);
            g_scale[o + 128] = inv;
            g_shift[o + 128] = bf[o] - mf[o] * inv;
        }
    }

    for (int t = threadIdx.x; t < 128 * 32; t += 128) {
        int c = t >> 5, n = t & 31;
        sf[c][n] = f[((size_t)b * 128 + c) * NPTS + n0 + n];
    }
    if (threadIdx.x < 96) {
        int n = threadIdx.x / 3, d = threadIdx.x % 3;
        sxyz[n][d] = xyz[((size_t)b * NPTS + n0 + n) * 3 + d];
    }
    __syncthreads();

    // geo: Ageo = (W03-W36).p ; Btgeo = W36.p
    {
        float w0 = W_geo[o * 6 + 0], w1 = W_geo[o * 6 + 1], w2 = W_geo[o * 6 + 2];
        float w3 = W_geo[o * 6 + 3], w4 = W_geo[o * 6 + 4], w5 = W_geo[o * 6 + 5];
        float wa = w0 - w3, wb = w1 - w4, wc = w2 - w5;
#pragma unroll 4
        for (int n = 0; n < 32; ++n) {
            float x = sxyz[n][0], y = sxyz[n][1], z = sxyz[n][2];
            size_t base = ((size_t)b * NPTS + n0 + n) * 128 + o;
            g_Ageo [base] = fmaf(wa, x, fmaf(wb, y, wc * z));
            g_Btgeo[base] = fmaf(w3, x, fmaf(w4, y, w5 * z));
        }
    }

    // feat: Afeat = (W1-W2)@f ; Btfeat = W2@f  (point-major out)
    float accA[32], accB[32];
#pragma unroll
    for (int n = 0; n < 32; ++n) { accA[n] = 0.f; accB[n] = 0.f; }

    for (int c = 0; c < 128; ++c) {
        float w1 = __ldg(&W_feat[o * 256 + c]);
        float w2 = __ldg(&W_feat[o * 256 + 128 + c]);
        float wm = w1 - w2;
        const float4* row = (const float4*)sf[c];
#pragma unroll
        for (int n4 = 0; n4 < 8; ++n4) {
            float4 v = row[n4];
            accA[n4 * 4 + 0] = fmaf(wm, v.x, accA[n4 * 4 + 0]);
            accB[n4 * 4 + 0] = fmaf(w2, v.x, accB[n4 * 4 + 0]);
            accA[n4 * 4 + 1] = fmaf(wm, v.y, accA[n4 * 4 + 1]);
            accB[n4 * 4 + 1] = fmaf(w2, v.y, accB[n4 * 4 + 1]);
            accA[n4 * 4 + 2] = fmaf(wm, v.z, accA[n4 * 4 + 2]);
            accB[n4 * 4 + 2] = fmaf(w2, v.z, accB[n4 * 4 + 2]);
            accA[n4 * 4 + 3] = fmaf(wm, v.w, accA[n4 * 4 + 3]);
            accB[n4 * 4 + 3] = fmaf(w2, v.w, accB[n4 * 4 + 3]);
        }
    }
#pragma unroll
    for (int n = 0; n < 32; ++n) {
        size_t base = ((size_t)b * NPTS + n0 + n) * 128 + o;
        g_Afeat [base] = accA[n];
        g_Btfeat[base] = accB[n];
    }
}

// ---------------- KNN: two-pass, 2 queries/warp, per-lane top-1 bound --------
// Pass 1: each lane keeps only its single smallest distance (1 FMNMX/cand).
// tau = 21st smallest of the 32 lane-minima (subset of all candidates =>
// tau >= true d21, valid conservative gate). Expected pass-2 queue ~34.
// Pass 2: collect all dist <= tau (ballot-append, index order), then exact
// top-21 by packed (flipped-dist, idx) key == lax.top_k(-dist) semantics.
#define KNN_CHUNK 1024
#define QCAP 96

__global__ void __launch_bounds__(256) knn_kernel(const float* __restrict__ xyz) {
    __shared__ float4 sc[KNN_CHUNK];
    __shared__ unsigned long long sQ[16][QCAP];

    int b    = blockIdx.y;
    int warp = threadIdx.x >> 5;
    int lane = threadIdx.x & 31;
    int q0   = blockIdx.x * 16 + warp * 2;
    int q1   = q0 + 1;

    const float* base = xyz + (size_t)b * NPTS * 3;
    float qx0 = base[q0 * 3 + 0], qy0 = base[q0 * 3 + 1], qz0 = base[q0 * 3 + 2];
    float qx1 = base[q1 * 3 + 0], qy1 = base[q1 * 3 + 1], qz1 = base[q1 * 3 + 2];
    float qd0 = fmaf(qx0, qx0, fmaf(qy0, qy0, qz0 * qz0));
    float qd1 = fmaf(qx1, qx1, fmaf(qy1, qy1, qz1 * qz1));

    float m0 = FINF, m1 = FINF;   // per-lane minimum distance per query

    // -------- pass 1 --------
    for (int cb = 0; cb < NPTS; cb += KNN_CHUNK) {
        __syncthreads();
        for (int i = threadIdx.x; i < KNN_CHUNK; i += 256) {
            int j = cb + i;
            float x = base[j * 3 + 0];
            float y = base[j * 3 + 1];
            float z = base[j * 3 + 2];
            float d2 = fmaf(x, x, fmaf(y, y, z * z));
            sc[i] = make_float4(x, y, z, d2);
        }
        __syncthreads();

#pragma unroll 4
        for (int i = lane; i < KNN_CHUNK; i += 32) {
            float4 c = sc[i];
            float dot0  = fmaf(qx0, c.x, fmaf(qy0, c.y, qz0 * c.z));
            float dist0 = fmaf(-2.f, dot0, qd0 + c.w);   // reference formula
            float dot1  = fmaf(qx1, c.x, fmaf(qy1, c.y, qz1 * c.z));
            float dist1 = fmaf(-2.f, dot1, qd1 + c.w);
            m0 = fminf(m0, dist0);
            m1 = fminf(m1, dist1);
        }
    }

    // tau = 21st smallest of the 32 lane minima (consume-one per round)
    float tau0, tau1;
    {
        float u = m0, mv;
#pragma unroll 1
        for (int r = 0; r < KNN; ++r) {
            mv = u;
#pragma unroll
            for (int off = 16; off; off >>= 1)
                mv = fminf(mv, __shfl_xor_sync(FULLM, mv, off));
            unsigned msk = __ballot_sync(FULLM, u == mv);
            if (lane == __ffs(msk) - 1) u = FINF;
        }
        tau0 = mv;
        u = m1;
#pragma unroll 1
        for (int r = 0; r < KNN; ++r) {
            mv = u;
#pragma unroll
            for (int off = 16; off; off >>= 1)
                mv = fminf(mv, __shfl_xor_sync(FULLM, mv, off));
            unsigned msk = __ballot_sync(FULLM, u == mv);
            if (lane == __ffs(msk) - 1) u = FINF;
        }
        tau1 = mv;
    }

    // -------- pass 2: collect all dist <= tau, in index order --------
    unsigned cnt0 = 0, cnt1 = 0;
    unsigned long long* Q0 = sQ[warp * 2 + 0];
    unsigned long long* Q1 = sQ[warp * 2 + 1];

    for (int cb = 0; cb < NPTS; cb += KNN_CHUNK) {
        __syncthreads();
        for (int i = threadIdx.x; i < KNN_CHUNK; i += 256) {
            int j = cb + i;
            float x = base[j * 3 + 0];
            float y = base[j * 3 + 1];
            float z = base[j * 3 + 2];
            float d2 = fmaf(x, x, fmaf(y, y, z * z));
            sc[i] = make_float4(x, y, z, d2);
        }
        __syncthreads();

#pragma unroll 4
        for (int i = lane; i < KNN_CHUNK; i += 32) {
            float4 c = sc[i];
            float dot0  = fmaf(qx0, c.x, fmaf(qy0, c.y, qz0 * c.z));
            float dist0 = fmaf(-2.f, dot0, qd0 + c.w);
            float dot1  = fmaf(qx1, c.x, fmaf(qy1, c.y, qz1 * c.z));
            float dist1 = fmaf(-2.f, dot1, qd1 + c.w);
            bool h0 = (dist0 <= tau0);
            bool h1 = (dist1 <= tau1);
            // single combined ballot on the fast path
            if (__ballot_sync(FULLM, h0 | h1)) {
                unsigned mk0 = __ballot_sync(FULLM, h0);
                unsigned mk1 = __ballot_sync(FULLM, h1);
                if (h0) {
                    unsigned u = __float_as_uint(dist0);
                    u ^= ((unsigned)((int)u >> 31)) | 0x80000000u;
                    unsigned off = cnt0 + __popc(mk0 & ((1u << lane) - 1u));
                    if (off < QCAP)
                        Q0[off] = ((unsigned long long)u << 32) | (unsigned)(cb + i);
                }
                if (h1) {
                    unsigned u = __float_as_uint(dist1);
                    u ^= ((unsigned)((int)u >> 31)) | 0x80000000u;
                    unsigned off = cnt1 + __popc(mk1 & ((1u << lane) - 1u));
                    if (off < QCAP)
                        Q1[off] = ((unsigned long long)u << 32) | (unsigned)(cb + i);
                }
                cnt0 += __popc(mk0);
                cnt1 += __popc(mk1);
            }
        }
    }
    __syncwarp();

    // -------- final: exact top-21 of each queue by (dist, idx) key --------
#pragma unroll 1
    for (int qi = 0; qi < 2; ++qi) {
        unsigned long long* Q = qi ? Q1 : Q0;
        int n = (int)(qi ? cnt1 : cnt0);
        if (n > QCAP) n = QCAP;
        unsigned long long k0 = (lane      < n) ? Q[lane]      : SENT;
        unsigned long long k1 = (lane + 32 < n) ? Q[lane + 32] : SENT;
        unsigned long long k2 = (lane + 64 < n) ? Q[lane + 64] : SENT;
        int myidx = 0;
#pragma unroll 1
        for (int r = 0; r < KNN; ++r) {
            unsigned long long lo = (k0 < k1) ? k0 : k1;
            unsigned long long best = (lo < k2) ? lo : k2;
            int bsrc = lane;
#pragma unroll
            for (int off = 16; off; off >>= 1) {
                unsigned long long ov = __shfl_xor_sync(FULLM, best, off);
                int os = __shfl_xor_sync(FULLM, bsrc, off);
                if (ov < best || (ov == best && os < bsrc)) { best = ov; bsrc = os; }
            }
            if (lane == r) myidx = (int)(best & 0xffffffffu);
            if (lane == bsrc) {           // keys unique (distinct idx)
                if      (k0 == best) k0 = SENT;
                else if (k1 == best) k1 = SENT;
                else                 k2 = SENT;
            }
        }
        if (lane < KNN)
            g_idx[((size_t)b * NPTS + (qi ? q1 : q0)) * KNN + lane] = myidx;
    }
}

// ---------------- gather-max + epilogue --------------------------------------
__device__ __forceinline__ float4 fmax4(float4 a, float4 b) {
    return make_float4(fmaxf(a.x, b.x), fmaxf(a.y, b.y),
                       fmaxf(a.z, b.z), fmaxf(a.w, b.w));
}

__global__ void __launch_bounds__(256) gather_max_kernel(float* __restrict__ out) {
    __shared__ int   sidx[32][KNN];
    __shared__ float sout[256 * 33];

    int b    = blockIdx.y;
    int n0   = blockIdx.x * 32;
    int warp = threadIdx.x >> 5;
    int lane = threadIdx.x & 31;

    for (int t = threadIdx.x; t < 32 * KNN; t += 256)
        sidx[t / KNN][t % KNN] = g_idx[((size_t)b * NPTS + n0) * KNN + t];
    __syncthreads();

    const float4* BG = (const float4*)g_Btgeo;
    const float4* BF = (const float4*)g_Btfeat;
    const float4* AG = (const float4*)g_Ageo;
    const float4* AF = (const float4*)g_Afeat;
    const float4* S4 = (const float4*)g_scale;
    const float4* H4 = (const float4*)g_shift;

    float4 scg = S4[lane],        shg = H4[lane];
    float4 scf = S4[32 + lane],   shf = H4[32 + lane];

    for (int pi = 0; pi < 4; ++pi) {
        int p = warp * 4 + pi;
        int n = n0 + p;
        float4 mg = make_float4(-3.4e38f, -3.4e38f, -3.4e38f, -3.4e38f);
        float4 mf = mg;
#pragma unroll
        for (int k = 0; k < KNN; ++k) {
            int j = sidx[p][k];
            size_t col = ((size_t)b * NPTS + j) * 32 + lane;
            mg = fmax4(mg, BG[col]);
            mf = fmax4(mf, BF[col]);
        }
        size_t acol = ((size_t)b * NPTS + n) * 32 + lane;
        float4 ag = AG[acol];
        float4 af = AF[acol];

        int cg = lane * 4;
        sout[(cg + 0) * 33 + p] = fmaxf(fmaf(mg.x + ag.x, scg.x, shg.x), 0.f);
        sout[(cg + 1) * 33 + p] = fmaxf(fmaf(mg.y + ag.y, scg.y, shg.y), 0.f);
        sout[(cg + 2) * 33 + p] = fmaxf(fmaf(mg.z + ag.z, scg.z, shg.z), 0.f);
        sout[(cg + 3) * 33 + p] = fmaxf(fmaf(mg.w + ag.w, scg.w, shg.w), 0.f);
        int cf = 128 + lane * 4;
        sout[(cf + 0) * 33 + p] = fmaxf(fmaf(mf.x + af.x, scf.x, shf.x), 0.f);
        sout[(cf + 1) * 33 + p] = fmaxf(fmaf(mf.y + af.y, scf.y, shf.y), 0.f);
        sout[(cf + 2) * 33 + p] = fmaxf(fmaf(mf.z + af.z, scf.z, shf.z), 0.f);
        sout[(cf + 3) * 33 + p] = fmaxf(fmaf(mf.w + af.w, scf.w, shf.w), 0.f);
    }
    __syncthreads();

    for (int c = warp; c < 256; c += 8)
        out[((size_t)b * 256 + c) * NPTS + n0 + lane] = sout[c * 33 + lane];
}

// ---------------- launch ------------------------------------------------------
extern "C" void kernel_launch(void* const* d_in, const int* in_sizes, int n_in,
                              void* d_out, int out_size) {
    const float* xyz    = (const float*)d_in[0];
    const float* f      = (const float*)d_in[1];
    const float* W_geo  = (const float*)d_in[2];
    const float* g_geo  = (const float*)d_in[3];
    const float* b_geo  = (const float*)d_in[4];
    const float* m_geo  = (const float*)d_in[5];
    const float* v_geo  = (const float*)d_in[6];
    const float* W_feat = (const float*)d_in[7];
    const float* g_feat = (const float*)d_in[8];
    const float* b_feat = (const float*)d_in[9];
    const float* m_feat = (const float*)d_in[10];
    const float* v_feat = (const float*)d_in[11];
    float* out = (float*)d_out;

    precompute_kernel<<<dim3(NPTS / 32, NB), 128>>>(
        xyz, f, W_geo, W_feat,
        g_geo, b_geo, m_geo, v_geo, g_feat, b_feat, m_feat, v_feat);
    knn_kernel<<<dim3(NPTS / 16, NB), 256>>>(xyz);
    gather_max_kernel<<<dim3(NPTS / 32, NB), 256>>>(out);
}

// round 8
// speedup vs baseline: 1.2711x; 1.0687x over previous
#include <cuda_runtime.h>
#include <cstdint>

#define NB   2
#define NPTS 8192
#define CIN  128
#define COUT 128
#define KNN  21
#define FULLM 0xffffffffu
#define SENT 0xFFFFFFFFFFFFFFFFull
#define FINF __int_as_float(0x7f800000)

// ---------------- scratch (device globals; no allocation allowed) -------------
__device__ __align__(16) float g_Ageo [NB * NPTS * 128];
__device__ __align__(16) float g_Btgeo[NB * NPTS * 128];
__device__ __align__(16) float g_Afeat[NB * NPTS * 128];
__device__ __align__(16) float g_Btfeat[NB * NPTS * 128];
__device__ int   g_idx[NB * NPTS * KNN];
__device__ __align__(16) float g_scale[256];
__device__ __align__(16) float g_shift[256];

// ------------- fused precompute: constants + geo + feat GEMM ------------------
// 256 threads: thread = (o = tid&127, nh = tid>>7); each thread computes
// channels o for 16 points (half the 32-point tile). 32 accumulators.
__global__ void __launch_bounds__(256) precompute_kernel(
        const float* __restrict__ xyz, const float* __restrict__ f,
        const float* __restrict__ W_geo, const float* __restrict__ W_feat,
        const float* __restrict__ gg, const float* __restrict__ bg,
        const float* __restrict__ mg, const float* __restrict__ vg,
        const float* __restrict__ gf, const float* __restrict__ bf,
        const float* __restrict__ mf, const float* __restrict__ vf) {
    __shared__ __align__(16) float sf[128][32];
    __shared__ float sxyz[32][3];
    int b  = blockIdx.y;
    int n0 = blockIdx.x * 32;
    int o  = threadIdx.x & 127;
    int nh = threadIdx.x >> 7;          // 0/1: points [nh*16, nh*16+16)

    // BN constants (one block only; 256 threads cover 256 channels)
    if (blockIdx.x == 0 && blockIdx.y == 0) {
        int c = threadIdx.x;
        if (c < 128) {
            float inv = gg[c] * rsqrtf(vg[c] + 1e-5f);
            g_scale[c] = inv;
            g_shift[c] = bg[c] - mg[c] * inv;
        } else {
            int oc = c - 128;
            float inv = gf[oc] * rsqrtf(vf[oc] + 1e-5f);
            g_scale[c] = inv;
            g_shift[c] = bf[oc] - mf[oc] * inv;
        }
    }

    for (int t = threadIdx.x; t < 128 * 32; t += 256) {
        int c = t >> 5, n = t & 31;
        sf[c][n] = f[((size_t)b * 128 + c) * NPTS + n0 + n];
    }
    if (threadIdx.x < 96) {
        int n = threadIdx.x / 3, d = threadIdx.x % 3;
        sxyz[n][d] = xyz[((size_t)b * NPTS + n0 + n) * 3 + d];
    }
    __syncthreads();

    // geo: Ageo = (W03-W36).p ; Btgeo = W36.p   (16 points per thread)
    {
        float w0 = W_geo[o * 6 + 0], w1 = W_geo[o * 6 + 1], w2 = W_geo[o * 6 + 2];
        float w3 = W_geo[o * 6 + 3], w4 = W_geo[o * 6 + 4], w5 = W_geo[o * 6 + 5];
        float wa = w0 - w3, wb = w1 - w4, wc = w2 - w5;
#pragma unroll 4
        for (int t = 0; t < 16; ++t) {
            int n = nh * 16 + t;
            float x = sxyz[n][0], y = sxyz[n][1], z = sxyz[n][2];
            size_t base = ((size_t)b * NPTS + n0 + n) * 128 + o;
            g_Ageo [base] = fmaf(wa, x, fmaf(wb, y, wc * z));
            g_Btgeo[base] = fmaf(w3, x, fmaf(w4, y, w5 * z));
        }
    }

    // feat: Afeat = (W1-W2)@f ; Btfeat = W2@f   (16 points per thread)
    float accA[16], accB[16];
#pragma unroll
    for (int n = 0; n < 16; ++n) { accA[n] = 0.f; accB[n] = 0.f; }

    const float4* Wrow = (const float4*)(W_feat + (size_t)o * 256);
#pragma unroll 4
    for (int c4 = 0; c4 < 32; ++c4) {
        float4 w1v = __ldg(&Wrow[c4]);
        float4 w2v = __ldg(&Wrow[32 + c4]);
        float w1s[4] = {w1v.x, w1v.y, w1v.z, w1v.w};
        float w2s[4] = {w2v.x, w2v.y, w2v.z, w2v.w};
#pragma unroll
        for (int cc = 0; cc < 4; ++cc) {
            float w2 = w2s[cc];
            float wm = w1s[cc] - w2;
            const float4* row = (const float4*)&sf[c4 * 4 + cc][nh * 16];
#pragma unroll
            for (int n4 = 0; n4 < 4; ++n4) {
                float4 v = row[n4];
                accA[n4 * 4 + 0] = fmaf(wm, v.x, accA[n4 * 4 + 0]);
                accB[n4 * 4 + 0] = fmaf(w2, v.x, accB[n4 * 4 + 0]);
                accA[n4 * 4 + 1] = fmaf(wm, v.y, accA[n4 * 4 + 1]);
                accB[n4 * 4 + 1] = fmaf(w2, v.y, accB[n4 * 4 + 1]);
                accA[n4 * 4 + 2] = fmaf(wm, v.z, accA[n4 * 4 + 2]);
                accB[n4 * 4 + 2] = fmaf(w2, v.z, accB[n4 * 4 + 2]);
                accA[n4 * 4 + 3] = fmaf(wm, v.w, accA[n4 * 4 + 3]);
                accB[n4 * 4 + 3] = fmaf(w2, v.w, accB[n4 * 4 + 3]);
            }
        }
    }
#pragma unroll
    for (int n = 0; n < 16; ++n) {
        size_t base = ((size_t)b * NPTS + n0 + nh * 16 + n) * 128 + o;
        g_Afeat [base] = accA[n];
        g_Btfeat[base] = accB[n];
    }
}

// ---------------- KNN: two-pass, 2 queries/warp, per-lane top-1 bound --------
// Pass 1: each lane keeps only its single smallest distance (1 FMNMX/cand).
// tau = 21st smallest of the 32 lane-minima (subset of all candidates =>
// tau >= true d21, valid conservative gate). Expected pass-2 queue ~34.
// Pass 2: collect all dist <= tau (ballot-append, index order), then exact
// top-21 by packed (flipped-dist, idx) key == lax.top_k(-dist) semantics.
#define KNN_CHUNK 1024
#define QCAP 96

__global__ void __launch_bounds__(256) knn_kernel(const float* __restrict__ xyz) {
    __shared__ float4 sc[KNN_CHUNK];
    __shared__ unsigned long long sQ[16][QCAP];

    int b    = blockIdx.y;
    int warp = threadIdx.x >> 5;
    int lane = threadIdx.x & 31;
    int q0   = blockIdx.x * 16 + warp * 2;
    int q1   = q0 + 1;

    const float* base = xyz + (size_t)b * NPTS * 3;
    float qx0 = base[q0 * 3 + 0], qy0 = base[q0 * 3 + 1], qz0 = base[q0 * 3 + 2];
    float qx1 = base[q1 * 3 + 0], qy1 = base[q1 * 3 + 1], qz1 = base[q1 * 3 + 2];
    float qd0 = fmaf(qx0, qx0, fmaf(qy0, qy0, qz0 * qz0));
    float qd1 = fmaf(qx1, qx1, fmaf(qy1, qy1, qz1 * qz1));

    float m0 = FINF, m1 = FINF;   // per-lane minimum distance per query

    // -------- pass 1 --------
    for (int cb = 0; cb < NPTS; cb += KNN_CHUNK) {
        __syncthreads();
        for (int i = threadIdx.x; i < KNN_CHUNK; i += 256) {
            int j = cb + i;
            float x = base[j * 3 + 0];
            float y = base[j * 3 + 1];
            float z = base[j * 3 + 2];
            float d2 = fmaf(x, x, fmaf(y, y, z * z));
            sc[i] = make_float4(x, y, z, d2);
        }
        __syncthreads();

#pragma unroll 4
        for (int i = lane; i < KNN_CHUNK; i += 32) {
            float4 c = sc[i];
            float dot0  = fmaf(qx0, c.x, fmaf(qy0, c.y, qz0 * c.z));
            float dist0 = fmaf(-2.f, dot0, qd0 + c.w);   // reference formula
            float dot1  = fmaf(qx1, c.x, fmaf(qy1, c.y, qz1 * c.z));
            float dist1 = fmaf(-2.f, dot1, qd1 + c.w);
            m0 = fminf(m0, dist0);
            m1 = fminf(m1, dist1);
        }
    }

    // tau = 21st smallest of the 32 lane minima (consume-one per round)
    float tau0, tau1;
    {
        float u = m0, mv;
#pragma unroll 1
        for (int r = 0; r < KNN; ++r) {
            mv = u;
#pragma unroll
            for (int off = 16; off; off >>= 1)
                mv = fminf(mv, __shfl_xor_sync(FULLM, mv, off));
            unsigned msk = __ballot_sync(FULLM, u == mv);
            if (lane == __ffs(msk) - 1) u = FINF;
        }
        tau0 = mv;
        u = m1;
#pragma unroll 1
        for (int r = 0; r < KNN; ++r) {
            mv = u;
#pragma unroll
            for (int off = 16; off; off >>= 1)
                mv = fminf(mv, __shfl_xor_sync(FULLM, mv, off));
            unsigned msk = __ballot_sync(FULLM, u == mv);
            if (lane == __ffs(msk) - 1) u = FINF;
        }
        tau1 = mv;
    }

    // -------- pass 2: collect all dist <= tau, in index order --------
    unsigned cnt0 = 0, cnt1 = 0;
    unsigned long long* Q0 = sQ[warp * 2 + 0];
    unsigned long long* Q1 = sQ[warp * 2 + 1];

    for (int cb = 0; cb < NPTS; cb += KNN_CHUNK) {
        __syncthreads();
        for (int i = threadIdx.x; i < KNN_CHUNK; i += 256) {
            int j = cb + i;
            float x = base[j * 3 + 0];
            float y = base[j * 3 + 1];
            float z = base[j * 3 + 2];
            float d2 = fmaf(x, x, fmaf(y, y, z * z));
            sc[i] = make_float4(x, y, z, d2);
        }
        __syncthreads();

#pragma unroll 4
        for (int i = lane; i < KNN_CHUNK; i += 32) {
            float4 c = sc[i];
            float dot0  = fmaf(qx0, c.x, fmaf(qy0, c.y, qz0 * c.z));
            float dist0 = fmaf(-2.f, dot0, qd0 + c.w);
            float dot1  = fmaf(qx1, c.x, fmaf(qy1, c.y, qz1 * c.z));
            float dist1 = fmaf(-2.f, dot1, qd1 + c.w);
            bool h0 = (dist0 <= tau0);
            bool h1 = (dist1 <= tau1);
            // single combined ballot on the fast path
            if (__ballot_sync(FULLM, h0 | h1)) {
                unsigned mk0 = __ballot_sync(FULLM, h0);
                unsigned mk1 = __ballot_sync(FULLM, h1);
                if (h0) {
                    unsigned u = __float_as_uint(dist0);
                    u ^= ((unsigned)((int)u >> 31)) | 0x80000000u;
                    unsigned off = cnt0 + __popc(mk0 & ((1u << lane) - 1u));
                    if (off < QCAP)
                        Q0[off] = ((unsigned long long)u << 32) | (unsigned)(cb + i);
                }
                if (h1) {
                    unsigned u = __float_as_uint(dist1);
                    u ^= ((unsigned)((int)u >> 31)) | 0x80000000u;
                    unsigned off = cnt1 + __popc(mk1 & ((1u << lane) - 1u));
                    if (off < QCAP)
                        Q1[off] = ((unsigned long long)u << 32) | (unsigned)(cb + i);
                }
                cnt0 += __popc(mk0);
                cnt1 += __popc(mk1);
            }
        }
    }
    __syncwarp();

    // -------- final: exact top-21 of each queue by (dist, idx) key --------
#pragma unroll 1
    for (int qi = 0; qi < 2; ++qi) {
        unsigned long long* Q = qi ? Q1 : Q0;
        int n = (int)(qi ? cnt1 : cnt0);
        if (n > QCAP) n = QCAP;
        unsigned long long k0 = (lane      < n) ? Q[lane]      : SENT;
        unsigned long long k1 = (lane + 32 < n) ? Q[lane + 32] : SENT;
        unsigned long long k2 = (lane + 64 < n) ? Q[lane + 64] : SENT;
        int myidx = 0;
#pragma unroll 1
        for (int r = 0; r < KNN; ++r) {
            unsigned long long lo = (k0 < k1) ? k0 : k1;
            unsigned long long best = (lo < k2) ? lo : k2;
            int bsrc = lane;
#pragma unroll
            for (int off = 16; off; off >>= 1) {
                unsigned long long ov = __shfl_xor_sync(FULLM, best, off);
                int os = __shfl_xor_sync(FULLM, bsrc, off);
                if (ov < best || (ov == best && os < bsrc)) { best = ov; bsrc = os; }
            }
            if (lane == r) myidx = (int)(best & 0xffffffffu);
            if (lane == bsrc) {           // keys unique (distinct idx)
                if      (k0 == best) k0 = SENT;
                else if (k1 == best) k1 = SENT;
                else                 k2 = SENT;
            }
        }
        if (lane < KNN)
            g_idx[((size_t)b * NPTS + (qi ? q1 : q0)) * KNN + lane] = myidx;
    }
}

// ---------------- gather-max + epilogue --------------------------------------
__device__ __forceinline__ float4 fmax4(float4 a, float4 b) {
    return make_float4(fmaxf(a.x, b.x), fmaxf(a.y, b.y),
                       fmaxf(a.z, b.z), fmaxf(a.w, b.w));
}

__global__ void __launch_bounds__(256) gather_max_kernel(float* __restrict__ out) {
    __shared__ int   sidx[32][KNN];
    __shared__ float sout[256 * 33];

    int b    = blockIdx.y;
    int n0   = blockIdx.x * 32;
    int warp = threadIdx.x >> 5;
    int lane = threadIdx.x & 31;

    for (int t = threadIdx.x; t < 32 * KNN; t += 256)
        sidx[t / KNN][t % KNN] = g_idx[((size_t)b * NPTS + n0) * KNN + t];
    __syncthreads();

    const float4* BG = (const float4*)g_Btgeo;
    const float4* BF = (const float4*)g_Btfeat;
    const float4* AG = (const float4*)g_Ageo;
    const float4* AF = (const float4*)g_Afeat;
    const float4* S4 = (const float4*)g_scale;
    const float4* H4 = (const float4*)g_shift;

    float4 scg = S4[lane],        shg = H4[lane];
    float4 scf = S4[32 + lane],   shf = H4[32 + lane];

    for (int pi = 0; pi < 4; ++pi) {
        int p = warp * 4 + pi;
        int n = n0 + p;
        float4 mg = make_float4(-3.4e38f, -3.4e38f, -3.4e38f, -3.4e38f);
        float4 mf = mg;
#pragma unroll
        for (int k = 0; k < KNN; ++k) {
            int j = sidx[p][k];
            size_t col = ((size_t)b * NPTS + j) * 32 + lane;
            mg = fmax4(mg, BG[col]);
            mf = fmax4(mf, BF[col]);
        }
        size_t acol = ((size_t)b * NPTS + n) * 32 + lane;
        float4 ag = AG[acol];
        float4 af = AF[acol];

        int cg = lane * 4;
        sout[(cg + 0) * 33 + p] = fmaxf(fmaf(mg.x + ag.x, scg.x, shg.x), 0.f);
        sout[(cg + 1) * 33 + p] = fmaxf(fmaf(mg.y + ag.y, scg.y, shg.y), 0.f);
        sout[(cg + 2) * 33 + p] = fmaxf(fmaf(mg.z + ag.z, scg.z, shg.z), 0.f);
        sout[(cg + 3) * 33 + p] = fmaxf(fmaf(mg.w + ag.w, scg.w, shg.w), 0.f);
        int cf = 128 + lane * 4;
        sout[(cf + 0) * 33 + p] = fmaxf(fmaf(mf.x + af.x, scf.x, shf.x), 0.f);
        sout[(cf + 1) * 33 + p] = fmaxf(fmaf(mf.y + af.y, scf.y, shf.y), 0.f);
        sout[(cf + 2) * 33 + p] = fmaxf(fmaf(mf.z + af.z, scf.z, shf.z), 0.f);
        sout[(cf + 3) * 33 + p] = fmaxf(fmaf(mf.w + af.w, scf.w, shf.w), 0.f);
    }
    __syncthreads();

    for (int c = warp; c < 256; c += 8)
        out[((size_t)b * 256 + c) * NPTS + n0 + lane] = sout[c * 33 + lane];
}

// ---------------- launch ------------------------------------------------------
extern "C" void kernel_launch(void* const* d_in, const int* in_sizes, int n_in,
                              void* d_out, int out_size) {
    const float* xyz    = (const float*)d_in[0];
    const float* f      = (const float*)d_in[1];
    const float* W_geo  = (const float*)d_in[2];
    const float* g_geo  = (const float*)d_in[3];
    const float* b_geo  = (const float*)d_in[4];
    const float* m_geo  = (const float*)d_in[5];
    const float* v_geo  = (const float*)d_in[6];
    const float* W_feat = (const float*)d_in[7];
    const float* g_feat = (const float*)d_in[8];
    const float* b_feat = (const float*)d_in[9];
    const float* m_feat = (const float*)d_in[10];
    const float* v_feat = (const float*)d_in[11];
    float* out = (float*)d_out;

    precompute_kernel<<<dim3(NPTS / 32, NB), 256>>>(
        xyz, f, W_geo, W_feat,
        g_geo, b_geo, m_geo, v_geo, g_feat, b_feat, m_feat, v_feat);
    knn_kernel<<<dim3(NPTS / 16, NB), 256>>>(xyz);
    gather_max_kernel<<<dim3(NPTS / 32, NB), 256>>>(out);
}